// round 10
// baseline (speedup 1.0000x reference)
#include <cuda_runtime.h>
#include <cuda_fp16.h>

#define NN 100000
#define EE 1600000
#define DD 64
#define SCAN_B 1024
#define NB ((NN + SCAN_B - 1) / SCAN_B)   // 98

// ---------------- scratch (static __device__, zero-initialized) -------------
__device__ int    g_deg_out[NN];
__device__ int    g_deg_in[NN];
__device__ float  g_norm_src[NN];
__device__ float  g_norm_dst[NN];
__device__ int    g_row_ptr[NN + 1];   // block-local exclusive; add g_bsum[i>>10]
__device__ int    g_fill[NN];
__device__ int    g_col[EE];
__device__ int    g_bsum[NB];
__device__ __half g_h[NN * DD];
__device__ float  g_bufA[NN * DD];
__device__ float  g_bufB[NN * DD];

// ---------------- degree histogram (deg/fill zero on entry: static zero-init
// on first run, re-zeroed inside k_scan1 on every run) -----------------------
__global__ void k_hist(const int* __restrict__ src, const int* __restrict__ dst) {
    int e = (blockIdx.x * blockDim.x + threadIdx.x) * 2;
    if (e + 1 < EE) {
        int s0 = src[e], s1 = src[e + 1];
        int d0 = dst[e], d1 = dst[e + 1];
        atomicAdd(&g_deg_out[s0], 1);
        atomicAdd(&g_deg_out[s1], 1);
        atomicAdd(&g_deg_in[d0], 1);
        atomicAdd(&g_deg_in[d1], 1);
    } else if (e < EE) {
        atomicAdd(&g_deg_out[src[e]], 1);
        atomicAdd(&g_deg_in[dst[e]], 1);
    }
}

// ---------------- scan1: block-local exclusive scan of deg_in + norms -------
// also read-then-clear deg arrays and zero g_fill for this call's k_fill.
__global__ void k_scan1() {
    __shared__ int sh[SCAN_B];
    int tid = threadIdx.x;
    int i   = blockIdx.x * SCAN_B + tid;
    int v   = 0;
    if (i < NN) {
        int din  = g_deg_in[i];
        int dout = g_deg_out[i];
        v = din;
        g_deg_in[i]  = 0;          // consumed; zero for next call's k_hist
        g_deg_out[i] = 0;
        g_fill[i]    = 0;          // zero before this call's k_fill
        if (din  < 1) din  = 1;
        if (dout < 1) dout = 1;
        g_norm_src[i] = rsqrtf((float)dout);
        g_norm_dst[i] = rsqrtf((float)din);
    }
    sh[tid] = v;
    __syncthreads();
    for (int off = 1; off < SCAN_B; off <<= 1) {
        int t = (tid >= off) ? sh[tid - off] : 0;
        __syncthreads();
        sh[tid] += t;
        __syncthreads();
    }
    int incl = sh[tid];
    if (i < NN) g_row_ptr[i] = incl - v;        // exclusive within block
    if (tid == SCAN_B - 1) g_bsum[blockIdx.x] = incl;   // block total
}

// scan2: exclusive-scan the 98 block totals in place.
// row_ptr[NN] gets the LAST BLOCK's own total so that
// row_ptr[NN] + g_bsum[NN>>10] == EE  (NN>>10 == NB-1 == 97).
__global__ void k_scan2() {
    __shared__ int sh[128];
    int tid = threadIdx.x;
    int v = (tid < NB) ? g_bsum[tid] : 0;
    sh[tid] = v;
    __syncthreads();
    for (int off = 1; off < 128; off <<= 1) {
        int t = (tid >= off) ? sh[tid - off] : 0;
        __syncthreads();
        sh[tid] += t;
        __syncthreads();
    }
    if (tid < NB) g_bsum[tid] = sh[tid] - v;    // exclusive
    if (tid == NB - 1) g_row_ptr[NN] = v;       // last block's own total
}

// ---------------- CSR fill (grouped by dst); bsum offset applied inline ------
__global__ void k_fill(const int* __restrict__ src, const int* __restrict__ dst) {
    int e = blockIdx.x * blockDim.x + threadIdx.x;
    if (e < EE) {
        int d   = dst[e];
        int pos = g_row_ptr[d] + g_bsum[d >> 10] + atomicAdd(&g_fill[d], 1);
        g_col[pos] = src[e];
    }
}

// ---------------- GEMM: h[n] = fp16( (x[n] * norm_src[n]) @ W ) --------------
// 128-row tiles, 128 threads. Thread (rc = tid>>3, g = tid&7) computes
// rows rc*8..rc*8+7, cols 8g..8g+7 (64 accumulators). Per-tile LDS.128 =
// 1024 warp-ops = 4096 cyc == FFMA floor (was 6144 at 8x4 blocking).
#define GR 128

__global__ void k_gemm(const float* __restrict__ x, const float* __restrict__ W,
                       __half* __restrict__ h) {
    __shared__ float4 Ws4[DD * 16];   // Ws4[k*16 + q], q = float4 col group
    __shared__ float4 xs4[GR * 16];   // xs4[row*16 + kq]
    int tid = threadIdx.x;            // 0..127

    {
        const float4* Wsrc = (const float4*)W;
        #pragma unroll
        for (int i = tid; i < DD * 16; i += 128) Ws4[i] = Wsrc[i];
    }

    int rc = tid >> 3;   // 0..15 (8-row chunk)
    int g  = tid & 7;    // 0..7  (8-col group: float4 cols 2g, 2g+1)

    const int n_tiles = (NN + GR - 1) / GR;
    for (int t = blockIdx.x; t < n_tiles; t += gridDim.x) {
        int base = t * GR;

        __syncthreads();   // prev tile's xs readers done (covers Ws on iter 0)
        #pragma unroll
        for (int i = 0; i < 16; i++) {
            int idx = tid + i * 128;       // 0..2047
            int row = idx >> 4;
            int kq  = idx & 15;
            int n   = base + row;
            float4 v = make_float4(0.f, 0.f, 0.f, 0.f);
            float ns = 0.f;
            if (n < NN) {
                v  = ((const float4*)x)[n * 16 + kq];
                ns = g_norm_src[n];
            }
            v.x *= ns; v.y *= ns; v.z *= ns; v.w *= ns;
            xs4[row * 16 + kq] = v;
        }
        __syncthreads();

        float4 accL[8], accH[8];
        #pragma unroll
        for (int j = 0; j < 8; j++) {
            accL[j] = make_float4(0.f, 0.f, 0.f, 0.f);
            accH[j] = make_float4(0.f, 0.f, 0.f, 0.f);
        }

        #pragma unroll
        for (int kq = 0; kq < 16; kq++) {
            float4 xv[8];
            #pragma unroll
            for (int j = 0; j < 8; j++) xv[j] = xs4[(rc * 8 + j) * 16 + kq];

            #pragma unroll
            for (int kk = 0; kk < 4; kk++) {
                float4 wl = Ws4[(4 * kq + kk) * 16 + 2 * g];
                float4 wh = Ws4[(4 * kq + kk) * 16 + 2 * g + 1];
                #pragma unroll
                for (int j = 0; j < 8; j++) {
                    float xk = (kk == 0) ? xv[j].x : (kk == 1) ? xv[j].y
                             : (kk == 2) ? xv[j].z : xv[j].w;
                    accL[j].x += xk * wl.x; accL[j].y += xk * wl.y;
                    accL[j].z += xk * wl.z; accL[j].w += xk * wl.w;
                    accH[j].x += xk * wh.x; accH[j].y += xk * wh.y;
                    accH[j].z += xk * wh.z; accH[j].w += xk * wh.w;
                }
            }
        }

        #pragma unroll
        for (int j = 0; j < 8; j++) {
            int n = base + rc * 8 + j;
            if (n < NN) {
                __half2 h0 = __floats2half2_rn(accL[j].x, accL[j].y);
                __half2 h1 = __floats2half2_rn(accL[j].z, accL[j].w);
                __half2 h2 = __floats2half2_rn(accH[j].x, accH[j].y);
                __half2 h3 = __floats2half2_rn(accH[j].z, accH[j].w);
                uint4 pk;
                pk.x = *(unsigned int*)&h0;
                pk.y = *(unsigned int*)&h1;
                pk.z = *(unsigned int*)&h2;
                pk.w = *(unsigned int*)&h3;
                ((uint4*)h)[n * 8 + g] = pk;   // 16B store: cols 8g..8g+7
            }
        }
    }
}

// ---------------- aggregation + epilogue ----------------
// one warp per node; lane owns 2 cols; 8 edges in flight.
// row_ptr is block-local; add g_bsum[idx>>10] inline.
__global__ void k_agg(const float* __restrict__ resid, const float* __restrict__ b,
                      float* __restrict__ out) {
    int warp = (blockIdx.x * blockDim.x + threadIdx.x) >> 5;
    int lane = threadIdx.x & 31;
    if (warp >= NN) return;

    int beg = g_row_ptr[warp] + g_bsum[warp >> 10];
    int end = g_row_ptr[warp + 1] + g_bsum[(warp + 1) >> 10];
    const __half2* h2 = (const __half2*)g_h;

    float2 a0 = make_float2(0.f, 0.f);
    float2 a1 = make_float2(0.f, 0.f);
    float2 a2 = make_float2(0.f, 0.f);
    float2 a3 = make_float2(0.f, 0.f);
    int i = beg;
    for (; i + 7 < end; i += 8) {
        int s0 = __ldg(&g_col[i]);
        int s1 = __ldg(&g_col[i + 1]);
        int s2 = __ldg(&g_col[i + 2]);
        int s3 = __ldg(&g_col[i + 3]);
        int s4 = __ldg(&g_col[i + 4]);
        int s5 = __ldg(&g_col[i + 5]);
        int s6 = __ldg(&g_col[i + 6]);
        int s7 = __ldg(&g_col[i + 7]);
        float2 v0 = __half22float2(h2[s0 * 32 + lane]);
        float2 v1 = __half22float2(h2[s1 * 32 + lane]);
        float2 v2 = __half22float2(h2[s2 * 32 + lane]);
        float2 v3 = __half22float2(h2[s3 * 32 + lane]);
        float2 v4 = __half22float2(h2[s4 * 32 + lane]);
        float2 v5 = __half22float2(h2[s5 * 32 + lane]);
        float2 v6 = __half22float2(h2[s6 * 32 + lane]);
        float2 v7 = __half22float2(h2[s7 * 32 + lane]);
        a0.x += v0.x; a0.y += v0.y;
        a1.x += v1.x; a1.y += v1.y;
        a2.x += v2.x; a2.y += v2.y;
        a3.x += v3.x; a3.y += v3.y;
        a0.x += v4.x; a0.y += v4.y;
        a1.x += v5.x; a1.y += v5.y;
        a2.x += v6.x; a2.y += v6.y;
        a3.x += v7.x; a3.y += v7.y;
    }
    if (i + 3 < end) {
        int s0 = __ldg(&g_col[i]);
        int s1 = __ldg(&g_col[i + 1]);
        int s2 = __ldg(&g_col[i + 2]);
        int s3 = __ldg(&g_col[i + 3]);
        float2 v0 = __half22float2(h2[s0 * 32 + lane]);
        float2 v1 = __half22float2(h2[s1 * 32 + lane]);
        float2 v2 = __half22float2(h2[s2 * 32 + lane]);
        float2 v3 = __half22float2(h2[s3 * 32 + lane]);
        a0.x += v0.x; a0.y += v0.y;
        a1.x += v1.x; a1.y += v1.y;
        a2.x += v2.x; a2.y += v2.y;
        a3.x += v3.x; a3.y += v3.y;
        i += 4;
    }
    for (; i < end; i++) {
        int s0 = __ldg(&g_col[i]);
        float2 v0 = __half22float2(h2[s0 * 32 + lane]);
        a0.x += v0.x; a0.y += v0.y;
    }
    float sx = (a0.x + a1.x) + (a2.x + a3.x);
    float sy = (a0.y + a1.y) + (a2.y + a3.y);

    float nd = g_norm_dst[warp];
    float2 bb = ((const float2*)b)[lane];
    float2 rr = ((const float2*)resid)[warp * 32 + lane];
    float2 o;
    o.x = fmaxf(sx * nd + bb.x, 0.f) + rr.x;
    o.y = fmaxf(sy * nd + bb.y, 0.f) + rr.y;
    ((float2*)out)[warp * 32 + lane] = o;
}

// ---------------- launch ----------------
extern "C" void kernel_launch(void* const* d_in, const int* in_sizes, int n_in,
                              void* d_out, int out_size) {
    const float* feat = (const float*)d_in[0];
    const int*   src  = (const int*)d_in[1];
    const int*   dst  = (const int*)d_in[2];
    // d_in[3] = etype (unused)
    const float* w1 = (const float*)d_in[4];
    const float* b1 = (const float*)d_in[5];
    const float* w2 = (const float*)d_in[6];
    const float* b2 = (const float*)d_in[7];
    const float* w3 = (const float*)d_in[8];
    const float* b3 = (const float*)d_in[9];
    float* out = (float*)d_out;

    void *ph = nullptr, *pa = nullptr, *pb = nullptr;
    cudaGetSymbolAddress(&ph, g_h);
    cudaGetSymbolAddress(&pa, g_bufA);
    cudaGetSymbolAddress(&pb, g_bufB);
    __half* h   = (__half*)ph;
    float* bufA = (float*)pa;
    float* bufB = (float*)pb;

    // lazily-created side stream + events: first call (the uncaptured
    // correctness run) creates them; every call issues IDENTICAL work.
    static cudaStream_t s_side = nullptr;
    static cudaEvent_t  ev_fork = nullptr, ev_join = nullptr;
    if (s_side == nullptr) {
        cudaStreamCreateWithFlags(&s_side, cudaStreamNonBlocking);
        cudaEventCreateWithFlags(&ev_fork, cudaEventDisableTiming);
        cudaEventCreateWithFlags(&ev_join, cudaEventDisableTiming);
    }

    const int gE    = (EE + 255) / 256;
    const int gE2   = (EE / 2 + 255) / 256;
    const int gAgg  = (NN * 32 + 255) / 256;
    const int gGemm = 592;   // 4 blocks/SM, grid-stride over 782 tiles

    // ---- setup: hist -> scan1 (norms ready; deg/fill re-zeroed) ----
    k_hist<<<gE2, 256>>>(src, dst);
    k_scan1<<<NB, SCAN_B>>>();

    // ---- fork: gemm1 (needs only norm_src) overlaps scan2/fill ----
    cudaEventRecord(ev_fork, 0);
    cudaStreamWaitEvent(s_side, ev_fork, 0);
    k_gemm<<<gGemm, 128, 0, s_side>>>(feat, w1, h);
    cudaEventRecord(ev_join, s_side);

    k_scan2<<<1, 128>>>();
    k_fill<<<gE, 256>>>(src, dst);

    // ---- join, then the serial layer chain ----
    cudaStreamWaitEvent(0, ev_join, 0);
    k_agg<<<gAgg, 256>>>(feat, b1, bufA);

    k_gemm<<<gGemm, 128>>>(bufA, w2, h);
    k_agg<<<gAgg, 256>>>(bufA, b2, bufB);

    k_gemm<<<gGemm, 128>>>(bufB, w3, h);
    k_agg<<<gAgg, 256>>>(bufB, b3, out);
}

// round 11
// speedup vs baseline: 1.0517x; 1.0517x over previous
#include <cuda_runtime.h>
#include <cuda_fp16.h>

#define NN 100000
#define EE 1600000
#define DD 64
#define SCAN_B 1024
#define NB ((NN + SCAN_B - 1) / SCAN_B)   // 98

// ---------------- scratch (static __device__, zero-initialized) -------------
__device__ int    g_deg_out[NN];
__device__ int    g_deg_in[NN];
__device__ float  g_norm_src[NN];
__device__ float  g_norm_dst[NN];
__device__ int    g_row_ptr[NN + 1];   // block-local exclusive; add g_bsum[i>>10]
__device__ int    g_fill[NN];
__device__ int    g_col[EE];
__device__ int    g_bsum[NB];
__device__ __half g_h[NN * DD];
__device__ float  g_bufA[NN * DD];
__device__ float  g_bufB[NN * DD];

// ---------------- degree histogram (deg/fill zero on entry: static zero-init
// on first run, re-zeroed inside k_scan1 on every run) -----------------------
__global__ void k_hist(const int* __restrict__ src, const int* __restrict__ dst) {
    int e = (blockIdx.x * blockDim.x + threadIdx.x) * 2;
    if (e + 1 < EE) {
        int s0 = src[e], s1 = src[e + 1];
        int d0 = dst[e], d1 = dst[e + 1];
        atomicAdd(&g_deg_out[s0], 1);
        atomicAdd(&g_deg_out[s1], 1);
        atomicAdd(&g_deg_in[d0], 1);
        atomicAdd(&g_deg_in[d1], 1);
    } else if (e < EE) {
        atomicAdd(&g_deg_out[src[e]], 1);
        atomicAdd(&g_deg_in[dst[e]], 1);
    }
}

// ---------------- scan1: block-local exclusive scan of deg_in + norms -------
// also read-then-clear deg arrays and zero g_fill for this call's k_fill.
__global__ void k_scan1() {
    __shared__ int sh[SCAN_B];
    int tid = threadIdx.x;
    int i   = blockIdx.x * SCAN_B + tid;
    int v   = 0;
    if (i < NN) {
        int din  = g_deg_in[i];
        int dout = g_deg_out[i];
        v = din;
        g_deg_in[i]  = 0;          // consumed; zero for next call's k_hist
        g_deg_out[i] = 0;
        g_fill[i]    = 0;          // zero before this call's k_fill
        if (din  < 1) din  = 1;
        if (dout < 1) dout = 1;
        g_norm_src[i] = rsqrtf((float)dout);
        g_norm_dst[i] = rsqrtf((float)din);
    }
    sh[tid] = v;
    __syncthreads();
    for (int off = 1; off < SCAN_B; off <<= 1) {
        int t = (tid >= off) ? sh[tid - off] : 0;
        __syncthreads();
        sh[tid] += t;
        __syncthreads();
    }
    int incl = sh[tid];
    if (i < NN) g_row_ptr[i] = incl - v;        // exclusive within block
    if (tid == SCAN_B - 1) g_bsum[blockIdx.x] = incl;   // block total
}

// scan2: exclusive-scan the 98 block totals in place.
// row_ptr[NN] gets the LAST BLOCK's own total so that
// row_ptr[NN] + g_bsum[NN>>10] == EE  (NN>>10 == NB-1 == 97).
__global__ void k_scan2() {
    __shared__ int sh[128];
    int tid = threadIdx.x;
    int v = (tid < NB) ? g_bsum[tid] : 0;
    sh[tid] = v;
    __syncthreads();
    for (int off = 1; off < 128; off <<= 1) {
        int t = (tid >= off) ? sh[tid - off] : 0;
        __syncthreads();
        sh[tid] += t;
        __syncthreads();
    }
    if (tid < NB) g_bsum[tid] = sh[tid] - v;    // exclusive
    if (tid == NB - 1) g_row_ptr[NN] = v;       // last block's own total
}

// ---------------- CSR fill (grouped by dst); bsum offset applied inline ------
__global__ void k_fill(const int* __restrict__ src, const int* __restrict__ dst) {
    int e = blockIdx.x * blockDim.x + threadIdx.x;
    if (e < EE) {
        int d   = dst[e];
        int pos = g_row_ptr[d] + g_bsum[d >> 10] + atomicAdd(&g_fill[d], 1);
        g_col[pos] = src[e];
    }
}

// ---------------- GEMM: h[n] = fp16( (x[n] * norm_src[n]) @ W ) --------------
// (R9's proven shape) 128-row tiles, 256 threads. Thread (rc = tid>>4,
// g = tid&15) computes rows rc*8..rc*8+7, cols 4g..4g+3 (32 accumulators).
// All shared reads are float4. smem = 16KB + 32KB = 48KB exact.
#define GR 128

__global__ void k_gemm(const float* __restrict__ x, const float* __restrict__ W,
                       __half* __restrict__ h) {
    __shared__ float4 Ws4[DD * 16];   // W row-major as float4: Ws4[k*16 + g]
    __shared__ float4 xs4[GR * 16];   // x tile: xs4[row*16 + kq]
    int tid = threadIdx.x;

    {
        const float4* Wsrc = (const float4*)W;
        #pragma unroll
        for (int i = tid; i < DD * 16; i += 256) Ws4[i] = Wsrc[i];
    }

    int rc = tid >> 4;   // 0..15  (8-row chunk)
    int g  = tid & 15;   // 0..15  (4-col group)

    const int n_tiles = (NN + GR - 1) / GR;
    for (int t = blockIdx.x; t < n_tiles; t += gridDim.x) {
        int base = t * GR;

        __syncthreads();   // xs readers of previous tile done (covers W on iter 0)
        #pragma unroll
        for (int i = 0; i < 8; i++) {
            int idx = tid + i * 256;       // 0..2047
            int row = idx >> 4;
            int kq  = idx & 15;
            int n   = base + row;
            float4 v = make_float4(0.f, 0.f, 0.f, 0.f);
            float ns = 0.f;
            if (n < NN) {
                v  = ((const float4*)x)[n * 16 + kq];
                ns = g_norm_src[n];
            }
            v.x *= ns; v.y *= ns; v.z *= ns; v.w *= ns;
            xs4[row * 16 + kq] = v;
        }
        __syncthreads();

        float4 acc[8];
        #pragma unroll
        for (int j = 0; j < 8; j++) acc[j] = make_float4(0.f, 0.f, 0.f, 0.f);

        #pragma unroll
        for (int kq = 0; kq < 16; kq++) {
            float4 w0 = Ws4[(4 * kq + 0) * 16 + g];
            float4 w1 = Ws4[(4 * kq + 1) * 16 + g];
            float4 w2 = Ws4[(4 * kq + 2) * 16 + g];
            float4 w3 = Ws4[(4 * kq + 3) * 16 + g];
            #pragma unroll
            for (int j = 0; j < 8; j++) {
                float4 xv = xs4[(rc * 8 + j) * 16 + kq];
                acc[j].x += xv.x * w0.x; acc[j].y += xv.x * w0.y;
                acc[j].z += xv.x * w0.z; acc[j].w += xv.x * w0.w;
                acc[j].x += xv.y * w1.x; acc[j].y += xv.y * w1.y;
                acc[j].z += xv.y * w1.z; acc[j].w += xv.y * w1.w;
                acc[j].x += xv.z * w2.x; acc[j].y += xv.z * w2.y;
                acc[j].z += xv.z * w2.z; acc[j].w += xv.z * w2.w;
                acc[j].x += xv.w * w3.x; acc[j].y += xv.w * w3.y;
                acc[j].z += xv.w * w3.z; acc[j].w += xv.w * w3.w;
            }
        }

        #pragma unroll
        for (int j = 0; j < 8; j++) {
            int n = base + rc * 8 + j;
            if (n < NN) {
                __half2 lo = __floats2half2_rn(acc[j].x, acc[j].y);
                __half2 hi = __floats2half2_rn(acc[j].z, acc[j].w);
                uint2 pk;
                pk.x = *(unsigned int*)&lo;
                pk.y = *(unsigned int*)&hi;
                ((uint2*)h)[n * 16 + g] = pk;   // 8B store: cols 4g..4g+3
            }
        }
    }
}

// ---------------- aggregation + epilogue ----------------
// one warp per node; lane owns 2 cols; 8 edges in flight.
// row_ptr is block-local; add g_bsum[idx>>10] inline.
__global__ void k_agg(const float* __restrict__ resid, const float* __restrict__ b,
                      float* __restrict__ out) {
    int warp = (blockIdx.x * blockDim.x + threadIdx.x) >> 5;
    int lane = threadIdx.x & 31;
    if (warp >= NN) return;

    int beg = g_row_ptr[warp] + g_bsum[warp >> 10];
    int end = g_row_ptr[warp + 1] + g_bsum[(warp + 1) >> 10];
    const __half2* h2 = (const __half2*)g_h;

    float2 a0 = make_float2(0.f, 0.f);
    float2 a1 = make_float2(0.f, 0.f);
    float2 a2 = make_float2(0.f, 0.f);
    float2 a3 = make_float2(0.f, 0.f);
    int i = beg;
    for (; i + 7 < end; i += 8) {
        int s0 = __ldg(&g_col[i]);
        int s1 = __ldg(&g_col[i + 1]);
        int s2 = __ldg(&g_col[i + 2]);
        int s3 = __ldg(&g_col[i + 3]);
        int s4 = __ldg(&g_col[i + 4]);
        int s5 = __ldg(&g_col[i + 5]);
        int s6 = __ldg(&g_col[i + 6]);
        int s7 = __ldg(&g_col[i + 7]);
        float2 v0 = __half22float2(h2[s0 * 32 + lane]);
        float2 v1 = __half22float2(h2[s1 * 32 + lane]);
        float2 v2 = __half22float2(h2[s2 * 32 + lane]);
        float2 v3 = __half22float2(h2[s3 * 32 + lane]);
        float2 v4 = __half22float2(h2[s4 * 32 + lane]);
        float2 v5 = __half22float2(h2[s5 * 32 + lane]);
        float2 v6 = __half22float2(h2[s6 * 32 + lane]);
        float2 v7 = __half22float2(h2[s7 * 32 + lane]);
        a0.x += v0.x; a0.y += v0.y;
        a1.x += v1.x; a1.y += v1.y;
        a2.x += v2.x; a2.y += v2.y;
        a3.x += v3.x; a3.y += v3.y;
        a0.x += v4.x; a0.y += v4.y;
        a1.x += v5.x; a1.y += v5.y;
        a2.x += v6.x; a2.y += v6.y;
        a3.x += v7.x; a3.y += v7.y;
    }
    if (i + 3 < end) {
        int s0 = __ldg(&g_col[i]);
        int s1 = __ldg(&g_col[i + 1]);
        int s2 = __ldg(&g_col[i + 2]);
        int s3 = __ldg(&g_col[i + 3]);
        float2 v0 = __half22float2(h2[s0 * 32 + lane]);
        float2 v1 = __half22float2(h2[s1 * 32 + lane]);
        float2 v2 = __half22float2(h2[s2 * 32 + lane]);
        float2 v3 = __half22float2(h2[s3 * 32 + lane]);
        a0.x += v0.x; a0.y += v0.y;
        a1.x += v1.x; a1.y += v1.y;
        a2.x += v2.x; a2.y += v2.y;
        a3.x += v3.x; a3.y += v3.y;
        i += 4;
    }
    for (; i < end; i++) {
        int s0 = __ldg(&g_col[i]);
        float2 v0 = __half22float2(h2[s0 * 32 + lane]);
        a0.x += v0.x; a0.y += v0.y;
    }
    float sx = (a0.x + a1.x) + (a2.x + a3.x);
    float sy = (a0.y + a1.y) + (a2.y + a3.y);

    float nd = g_norm_dst[warp];
    float2 bb = ((const float2*)b)[lane];
    float2 rr = ((const float2*)resid)[warp * 32 + lane];
    float2 o;
    o.x = fmaxf(sx * nd + bb.x, 0.f) + rr.x;
    o.y = fmaxf(sy * nd + bb.y, 0.f) + rr.y;
    ((float2*)out)[warp * 32 + lane] = o;
}

// ---------------- launch ----------------
extern "C" void kernel_launch(void* const* d_in, const int* in_sizes, int n_in,
                              void* d_out, int out_size) {
    const float* feat = (const float*)d_in[0];
    const int*   src  = (const int*)d_in[1];
    const int*   dst  = (const int*)d_in[2];
    // d_in[3] = etype (unused)
    const float* w1 = (const float*)d_in[4];
    const float* b1 = (const float*)d_in[5];
    const float* w2 = (const float*)d_in[6];
    const float* b2 = (const float*)d_in[7];
    const float* w3 = (const float*)d_in[8];
    const float* b3 = (const float*)d_in[9];
    float* out = (float*)d_out;

    void *ph = nullptr, *pa = nullptr, *pb = nullptr;
    cudaGetSymbolAddress(&ph, g_h);
    cudaGetSymbolAddress(&pa, g_bufA);
    cudaGetSymbolAddress(&pb, g_bufB);
    __half* h   = (__half*)ph;
    float* bufA = (float*)pa;
    float* bufB = (float*)pb;

    // lazily-created side stream + events: first call (the uncaptured
    // correctness run) creates them; every call issues IDENTICAL work.
    static cudaStream_t s_side = nullptr;
    static cudaEvent_t  ev_fork = nullptr, ev_join = nullptr;
    if (s_side == nullptr) {
        cudaStreamCreateWithFlags(&s_side, cudaStreamNonBlocking);
        cudaEventCreateWithFlags(&ev_fork, cudaEventDisableTiming);
        cudaEventCreateWithFlags(&ev_join, cudaEventDisableTiming);
    }

    const int gE    = (EE + 255) / 256;
    const int gE2   = (EE / 2 + 255) / 256;
    const int gAgg  = (NN * 32 + 255) / 256;
    const int gGemm = (NN + GR - 1) / GR;   // 782, one tile per block

    // ---- setup: hist -> scan1 (norms ready; deg/fill re-zeroed) ----
    k_hist<<<gE2, 256>>>(src, dst);
    k_scan1<<<NB, SCAN_B>>>();

    // ---- fork: gemm1 (needs only norm_src) overlaps scan2/fill ----
    cudaEventRecord(ev_fork, 0);
    cudaStreamWaitEvent(s_side, ev_fork, 0);
    k_gemm<<<gGemm, 256, 0, s_side>>>(feat, w1, h);
    cudaEventRecord(ev_join, s_side);

    k_scan2<<<1, 128>>>();
    k_fill<<<gE, 256>>>(src, dst);

    // ---- join, then the serial layer chain ----
    cudaStreamWaitEvent(0, ev_join, 0);
    k_agg<<<gAgg, 256>>>(feat, b1, bufA);

    k_gemm<<<gGemm, 256>>>(bufA, w2, h);
    k_agg<<<gAgg, 256>>>(bufA, b2, bufB);

    k_gemm<<<gGemm, 256>>>(bufB, w3, h);
    k_agg<<<gAgg, 256>>>(bufB, b3, out);
}